// round 6
// baseline (speedup 1.0000x reference)
#include <cuda_runtime.h>
#include <math.h>

// ---------------- problem constants ----------------
#define BT_TOT   3840          // B*NSZ*T
#define NSAMP    72960         // BT_TOT * C
#define TSEQ     120
#define NSEQ     32            // B*NSZ
#define HID      16

// ---------------- scratch (device globals; no allocation allowed) ----------------
__device__ float g_tok[BT_TOT * 19 * 32];      // CNN features + pos_emb (rows 0..18)
__device__ float g_hm[BT_TOT * 32];            // marker token after transformer
__device__ float g_h[2 * NSEQ * TSEQ * HID];   // LSTM hidden states fwd/bwd

// allowed-attention bitmasks (bit k set = query row attends key k); row19 = all
__constant__ unsigned MASK20[20] = {
    0x1Fu,    0x73u,    0x1DDu,   0x33Du,   0x23Bu,
    0x67Au,   0xC76u,   0x3984u,  0x779Cu,  0xE738u,
    0x1CF70u, 0x18CC0u, 0x33180u, 0x2F380u, 0x6E700u,
    0x5EE00u, 0x59C00u, 0x67000u, 0x7C000u, 0xFFFFFu
};

// =====================================================================
// Kernel 1 (LITERAL REWRITE): per-channel CNN. thread = (sample, oc).
// conv1: 1->32, k5 s5 (200->40), relu, pool2 -> 20
// conv2: 32->32, k5 s2 (20->8), relu, pool2 -> 4, mean -> feat[32]
// =====================================================================
__global__ __launch_bounds__(128) void k1_cnn(
    const float* __restrict__ x, const float* __restrict__ pos_emb,
    const float* __restrict__ c1w, const float* __restrict__ c1b,
    const float* __restrict__ c2w, const float* __restrict__ c2b)
{
    __shared__ float s_p1[4][32][20];

    const int tid = threadIdx.x, ls = tid >> 5, oc = tid & 31;
    const int s = blockIdx.x * 4 + ls;          // sample id < NSAMP
    const float* xp = x + (size_t)s * 200;

    const float w0 = c1w[oc * 5 + 0], w1v = c1w[oc * 5 + 1], w2v = c1w[oc * 5 + 2],
                w3v = c1w[oc * 5 + 3], w4v = c1w[oc * 5 + 4];
    const float b1v = c1b[oc];

#pragma unroll
    for (int j = 0; j < 20; j++) {
        const float* xx = xp + 10 * j;
        float o0 = b1v, o1 = b1v;
        o0 = fmaf(xx[0], w0,  o0); o0 = fmaf(xx[1], w1v, o0);
        o0 = fmaf(xx[2], w2v, o0); o0 = fmaf(xx[3], w3v, o0);
        o0 = fmaf(xx[4], w4v, o0);
        o1 = fmaf(xx[5], w0,  o1); o1 = fmaf(xx[6], w1v, o1);
        o1 = fmaf(xx[7], w2v, o1); o1 = fmaf(xx[8], w3v, o1);
        o1 = fmaf(xx[9], w4v, o1);
        s_p1[ls][oc][j] = fmaxf(fmaxf(o0, o1), 0.f);
    }
    __syncthreads();

    float acc[8];
    const float b2v = c2b[oc];
#pragma unroll
    for (int p = 0; p < 8; p++) acc[p] = b2v;

    for (int ic = 0; ic < 32; ic++) {
        const float* wr = c2w + oc * 160 + ic * 5;
        const float u0 = wr[0], u1 = wr[1], u2 = wr[2], u3 = wr[3], u4 = wr[4];
        const float* pr = s_p1[ls][ic];
#pragma unroll
        for (int p = 0; p < 8; p++) {
            float a = acc[p];
            a = fmaf(pr[2 * p + 0], u0, a);
            a = fmaf(pr[2 * p + 1], u1, a);
            a = fmaf(pr[2 * p + 2], u2, a);
            a = fmaf(pr[2 * p + 3], u3, a);
            a = fmaf(pr[2 * p + 4], u4, a);
            acc[p] = a;
        }
    }
    float f = 0.f;
#pragma unroll
    for (int j = 0; j < 4; j++)
        f += fmaxf(fmaxf(acc[2 * j], 0.f), fmaxf(acc[2 * j + 1], 0.f));
    f *= 0.25f;

    const int bt = s / 19, c = s - bt * 19;
    g_tok[bt * 608 + c * 32 + oc] = f + pos_emb[c * 32 + oc];
}

// =====================================================================
// Kernel 2: transformer layer. ONE bt per block, 640 threads,
// one scalar task per thread. Weights transposed on load from the
// ORIGINAL input arrays (no prep kernel).
// =====================================================================
#define SM_WQT  0
#define SM_WKT  1024
#define SM_WVT  2048
#define SM_WOT  3072
#define SM_W1T  4096
#define SM_W2T  8192
#define SM_BQ   12288
#define SM_BK   12320
#define SM_BV   12352
#define SM_BO   12384
#define SM_B1   12416
#define SM_B2   12544
#define SM_LN1G 12576
#define SM_LN1B 12608
#define SM_LN2G 12640
#define SM_LN2B 12672
#define SM_TOK  12704
#define SM_Q    13364
#define SM_K    14024
#define SM_V    14684
#define SM_ATTN 15344
#define SM_TOK2 16004
#define SM_HIDN 16664          // 20*129 = 2580
#define SM_RES  19244          // 660
#define K2_SMEM_FLOATS 19904
#define K2_SMEM_BYTES  (K2_SMEM_FLOATS * 4)

__global__ __launch_bounds__(640) void k2_transformer(
    const float* __restrict__ pos_emb,
    const float* __restrict__ wq, const float* __restrict__ bq,
    const float* __restrict__ wk, const float* __restrict__ bk,
    const float* __restrict__ wv, const float* __restrict__ bv,
    const float* __restrict__ wo, const float* __restrict__ bo,
    const float* __restrict__ ln1g, const float* __restrict__ ln1b,
    const float* __restrict__ w1,  const float* __restrict__ b1,
    const float* __restrict__ w2,  const float* __restrict__ b2,
    const float* __restrict__ ln2g, const float* __restrict__ ln2b,
    float* __restrict__ out_hc)
{
    extern __shared__ float sm[];
    const int tid = threadIdx.x;
    const int bt  = blockIdx.x;

    // ---- transpose-on-load weights from original arrays ----
    for (int i = tid; i < 1024; i += 640) {
        int d = i >> 5, j = i & 31;              // src[d][j]
        sm[SM_WQT + j * 32 + d] = wq[i];
        sm[SM_WKT + j * 32 + d] = wk[i];
        sm[SM_WVT + j * 32 + d] = wv[i];
        sm[SM_WOT + j * 32 + d] = wo[i];
    }
    for (int i = tid; i < 4096; i += 640) {
        int h = i >> 5, j = i & 31;              // w1[h][j]
        sm[SM_W1T + j * 128 + h] = w1[i];
    }
    for (int i = tid; i < 4096; i += 640) {
        int d = i >> 7, h = i & 127;             // w2[d][h]
        sm[SM_W2T + h * 32 + d] = w2[i];
    }
    if (tid < 32) {
        sm[SM_BQ + tid] = bq[tid];   sm[SM_BK + tid] = bk[tid];
        sm[SM_BV + tid] = bv[tid];   sm[SM_BO + tid] = bo[tid];
        sm[SM_B2 + tid] = b2[tid];
        sm[SM_LN1G + tid] = ln1g[tid]; sm[SM_LN1B + tid] = ln1b[tid];
        sm[SM_LN2G + tid] = ln2g[tid]; sm[SM_LN2B + tid] = ln2b[tid];
    } else if (tid >= 64 && tid < 192) {
        sm[SM_B1 + tid - 64] = b1[tid - 64];
    }
    // tokens: r<19 from CNN, r=19 = pos_emb row 19
    {
        int r = tid >> 5, d = tid & 31;          // tid < 640 -> r < 20
        float v = (r < 19) ? g_tok[bt * 608 + r * 32 + d] : pos_emb[608 + d];
        sm[SM_TOK + r * 33 + d] = v;
    }
    __syncthreads();

    // ---- QKV ----
    {
        int r = tid >> 5, d = tid & 31;
        float aq = sm[SM_BQ + d], ak = sm[SM_BK + d], av = sm[SM_BV + d];
#pragma unroll
        for (int j = 0; j < 32; j++) {
            float b = sm[SM_TOK + r * 33 + j];
            aq = fmaf(b, sm[SM_WQT + j * 32 + d], aq);
            ak = fmaf(b, sm[SM_WKT + j * 32 + d], ak);
            av = fmaf(b, sm[SM_WVT + j * 32 + d], av);
        }
        sm[SM_Q + r * 33 + d] = aq;
        sm[SM_K + r * 33 + d] = ak;
        sm[SM_V + r * 33 + d] = av;
    }
    __syncthreads();

    // ---- masked attention: thread (qi, head), tid < 160 ----
    if (tid < 160) {
        int qi = tid >> 3, h4 = (tid & 7) << 2;
        float q0 = sm[SM_Q + qi * 33 + h4 + 0] * 0.5f;   // 1/sqrt(4) folded
        float q1 = sm[SM_Q + qi * 33 + h4 + 1] * 0.5f;
        float q2 = sm[SM_Q + qi * 33 + h4 + 2] * 0.5f;
        float q3 = sm[SM_Q + qi * 33 + h4 + 3] * 0.5f;
        unsigned msk = MASK20[qi];
        float l[20], mx = -3.0e38f;
#pragma unroll
        for (int kt = 0; kt < 20; kt++) {
            float sc = q0 * sm[SM_K + kt * 33 + h4 + 0];
            sc = fmaf(q1, sm[SM_K + kt * 33 + h4 + 1], sc);
            sc = fmaf(q2, sm[SM_K + kt * 33 + h4 + 2], sc);
            sc = fmaf(q3, sm[SM_K + kt * 33 + h4 + 3], sc);
            l[kt] = ((msk >> kt) & 1u) ? sc : -1.0e9f;
            mx = fmaxf(mx, l[kt]);
        }
        float sum = 0.f;
#pragma unroll
        for (int kt = 0; kt < 20; kt++) { l[kt] = __expf(l[kt] - mx); sum += l[kt]; }
        float inv = 1.f / sum;
#pragma unroll
        for (int d = 0; d < 4; d++) {
            float a = 0.f;
#pragma unroll
            for (int kt = 0; kt < 20; kt++)
                a = fmaf(l[kt], sm[SM_V + kt * 33 + h4 + d], a);
            sm[SM_ATTN + qi * 33 + h4 + d] = a * inv;
        }
    }
    __syncthreads();

    // ---- attn @ woT + bo + residual -> RES ----
    {
        int r = tid >> 5, d = tid & 31;
        float acc = sm[SM_BO + d];
#pragma unroll
        for (int j = 0; j < 32; j++)
            acc = fmaf(sm[SM_ATTN + r * 33 + j], sm[SM_WOT + j * 32 + d], acc);
        sm[SM_RES + r * 33 + d] = sm[SM_TOK + r * 33 + d] + acc;
    }
    __syncthreads();

    // ---- LayerNorm1 (one thread per token) ----
    if (tid < 20) {
        const int r = tid;
        float mu = 0.f;
#pragma unroll
        for (int d = 0; d < 32; d++) mu += sm[SM_RES + r * 33 + d];
        mu *= 0.03125f;
        float var = 0.f;
#pragma unroll
        for (int d = 0; d < 32; d++) {
            float t = sm[SM_RES + r * 33 + d] - mu; var = fmaf(t, t, var);
        }
        var *= 0.03125f;
        float rinv = rsqrtf(var + 1e-5f);
#pragma unroll
        for (int d = 0; d < 32; d++)
            sm[SM_TOK2 + r * 33 + d] =
                (sm[SM_RES + r * 33 + d] - mu) * rinv * sm[SM_LN1G + d] + sm[SM_LN1B + d];
    }
    __syncthreads();

    // ---- FF1 (32->128, relu): 2560 outputs, 4 per thread ----
#pragma unroll
    for (int p = 0; p < 4; p++) {
        int idx = tid + p * 640;          // < 2560
        int r = idx >> 7, h = idx & 127;
        float acc = sm[SM_B1 + h];
#pragma unroll
        for (int j = 0; j < 32; j++)
            acc = fmaf(sm[SM_TOK2 + r * 33 + j], sm[SM_W1T + j * 128 + h], acc);
        sm[SM_HIDN + r * 129 + h] = fmaxf(acc, 0.f);
    }
    __syncthreads();

    // ---- FF2 (128->32) + residual -> RES ----
    {
        int r = tid >> 5, d = tid & 31;
        float acc = sm[SM_B2 + d];
#pragma unroll
        for (int j = 0; j < 128; j++)
            acc = fmaf(sm[SM_HIDN + r * 129 + j], sm[SM_W2T + j * 32 + d], acc);
        sm[SM_RES + r * 33 + d] = sm[SM_TOK2 + r * 33 + d] + acc;
    }
    __syncthreads();

    // ---- LayerNorm2 -> global outputs (one thread per token) ----
    if (tid < 20) {
        const int r = tid;
        float mu = 0.f;
#pragma unroll
        for (int d = 0; d < 32; d++) mu += sm[SM_RES + r * 33 + d];
        mu *= 0.03125f;
        float var = 0.f;
#pragma unroll
        for (int d = 0; d < 32; d++) {
            float t = sm[SM_RES + r * 33 + d] - mu; var = fmaf(t, t, var);
        }
        var *= 0.03125f;
        float rinv = rsqrtf(var + 1e-5f);
#pragma unroll
        for (int d = 0; d < 32; d++) {
            float o = (sm[SM_RES + r * 33 + d] - mu) * rinv * sm[SM_LN2G + d] + sm[SM_LN2B + d];
            if (r < 19) out_hc[bt * 608 + r * 32 + d] = o;
            else        g_hm[bt * 32 + d] = o;
        }
    }
}

// =====================================================================
// Kernel 3: BiLSTM, 1 block per sequence, 128 threads.
// dir = tid/64, j = tid%64 = gate row. Gates exchanged via shared memory.
// =====================================================================
__global__ __launch_bounds__(128) void k3_lstm(
    const float* __restrict__ wih_f, const float* __restrict__ whh_f,
    const float* __restrict__ bih_f, const float* __restrict__ bhh_f,
    const float* __restrict__ wih_b, const float* __restrict__ whh_b,
    const float* __restrict__ bih_b, const float* __restrict__ bhh_b)
{
    __shared__ float s_hm[TSEQ * 32];
    __shared__ float s_g[2][64];
    __shared__ float s_h[2][16];

    const int tid = threadIdx.x;
    const int dir = tid >> 6;            // 0 fwd, 1 bwd
    const int j   = tid & 63;            // gate row 0..63
    const int seq = blockIdx.x;

    for (int i = tid; i < TSEQ * 32; i += 128)
        s_hm[i] = g_hm[seq * TSEQ * 32 + i];

    const float* wih = dir ? wih_b : wih_f;
    const float* whh = dir ? whh_b : whh_f;
    const float* bih = dir ? bih_b : bih_f;
    const float* bhh = dir ? bhh_b : bhh_f;

    float wx[32], wh[16];
#pragma unroll
    for (int k = 0; k < 32; k++) wx[k] = wih[j * 32 + k];
#pragma unroll
    for (int k = 0; k < 16; k++) wh[k] = whh[j * 16 + k];
    const float bias = bih[j] + bhh[j];

    if (j < 16) s_h[dir][j] = 0.f;
    float c = 0.f;
    __syncthreads();

    for (int step = 0; step < TSEQ; step++) {
        const int t = dir ? (TSEQ - 1 - step) : step;
        float g = bias;
        const float* xp = &s_hm[t * 32];
#pragma unroll
        for (int k = 0; k < 32; k++) g = fmaf(xp[k], wx[k], g);
#pragma unroll
        for (int k = 0; k < 16; k++) g = fmaf(s_h[dir][k], wh[k], g);
        s_g[dir][j] = g;
        __syncthreads();
        if (j < 16) {
            float ig = 1.f / (1.f + __expf(-s_g[dir][j]));
            float ff = 1.f / (1.f + __expf(-s_g[dir][16 + j]));
            float gg = tanhf(s_g[dir][32 + j]);
            float oo = 1.f / (1.f + __expf(-s_g[dir][48 + j]));
            c = ff * c + ig * gg;
            float h = oo * tanhf(c);
            s_h[dir][j] = h;
            g_h[dir * (NSEQ * TSEQ * HID) + (seq * TSEQ + t) * HID + j] = h;
        }
        __syncthreads();
    }
}

// =====================================================================
// Kernel 4 (REWRITE): final linear head. block = seq, thread = t.
// =====================================================================
__global__ __launch_bounds__(TSEQ) void k4_linear(
    const float* __restrict__ lin_w,
    const float* __restrict__ lin_b,
    float* __restrict__ out)
{
    const int seq = blockIdx.x, t = threadIdx.x;
    const int bt = seq * TSEQ + t;
    const float* hf = &g_h[bt * HID];
    const float* hb = &g_h[NSEQ * TSEQ * HID + bt * HID];
    float a0 = lin_b[0], a1 = lin_b[1];
#pragma unroll
    for (int j = 0; j < 16; j++) {
        float f = hf[j], b = hb[j];
        a0 = fmaf(f, lin_w[j],      a0);
        a0 = fmaf(b, lin_w[16 + j], a0);
        a1 = fmaf(f, lin_w[32 + j], a1);
        a1 = fmaf(b, lin_w[48 + j], a1);
    }
    out[bt * 2 + 0] = a0;
    out[bt * 2 + 1] = a1;
}

// =====================================================================
extern "C" void kernel_launch(void* const* d_in, const int* in_sizes, int n_in,
                              void* d_out, int out_size)
{
    const float* x       = (const float*)d_in[0];
    const float* pos_emb = (const float*)d_in[1];
    const float* c1w     = (const float*)d_in[2];
    const float* c1b     = (const float*)d_in[3];
    const float* c2w     = (const float*)d_in[4];
    const float* c2b     = (const float*)d_in[5];
    const float* wq      = (const float*)d_in[6];
    const float* bq      = (const float*)d_in[7];
    const float* wk      = (const float*)d_in[8];
    const float* bk      = (const float*)d_in[9];
    const float* wv      = (const float*)d_in[10];
    const float* bv      = (const float*)d_in[11];
    const float* wo      = (const float*)d_in[12];
    const float* bo      = (const float*)d_in[13];
    const float* ln1g    = (const float*)d_in[14];
    const float* ln1b    = (const float*)d_in[15];
    const float* w1      = (const float*)d_in[16];
    const float* b1      = (const float*)d_in[17];
    const float* w2      = (const float*)d_in[18];
    const float* b2      = (const float*)d_in[19];
    const float* ln2g    = (const float*)d_in[20];
    const float* ln2b    = (const float*)d_in[21];
    const float* wih_f   = (const float*)d_in[22];
    const float* whh_f   = (const float*)d_in[23];
    const float* bih_f   = (const float*)d_in[24];
    const float* bhh_f   = (const float*)d_in[25];
    const float* wih_b   = (const float*)d_in[26];
    const float* whh_b   = (const float*)d_in[27];
    const float* bih_b   = (const float*)d_in[28];
    const float* bhh_b   = (const float*)d_in[29];
    const float* lin_w   = (const float*)d_in[30];
    const float* lin_b   = (const float*)d_in[31];

    float* out = (float*)d_out;   // [0,7680): proba ; [7680,...): h_c_out

    cudaFuncSetAttribute(k2_transformer,
                         cudaFuncAttributeMaxDynamicSharedMemorySize,
                         K2_SMEM_BYTES);

    k1_cnn<<<NSAMP / 4, 128>>>(x, pos_emb, c1w, c1b, c2w, c2b);
    k2_transformer<<<BT_TOT, 640, K2_SMEM_BYTES>>>(
        pos_emb, wq, bq, wk, bk, wv, bv, wo, bo,
        ln1g, ln1b, w1, b1, w2, b2, ln2g, ln2b,
        out + 7680);
    k3_lstm<<<NSEQ, 128>>>(wih_f, whh_f, bih_f, bhh_f,
                           wih_b, whh_b, bih_b, bhh_b);
    k4_linear<<<NSEQ, TSEQ>>>(lin_w, lin_b, out);
}

// round 13
// speedup vs baseline: 3.4408x; 3.4408x over previous
#include <cuda_runtime.h>
#include <math.h>

// ---------------- problem constants ----------------
#define BT_TOT   3840          // B*NSZ*T
#define NSAMP    72960         // BT_TOT * C
#define TSEQ     120
#define NSEQ     32            // B*NSZ
#define HID      16

// ---------------- scratch (device globals; no allocation allowed) ----------------
__device__ float g_tok[BT_TOT * 19 * 32];      // CNN features + pos_emb (rows 0..18)
__device__ float g_hm[BT_TOT * 32];            // marker token after transformer
__device__ float g_h[2 * NSEQ * TSEQ * HID];   // LSTM hidden states fwd/bwd

// allowed-attention bitmasks (bit k set = query row attends key k); row19 = all
__constant__ unsigned MASK20[20] = {
    0x1Fu,    0x73u,    0x1DDu,   0x33Du,   0x23Bu,
    0x67Au,   0xC76u,   0x3984u,  0x779Cu,  0xE738u,
    0x1CF70u, 0x18CC0u, 0x33180u, 0x2F380u, 0x6E700u,
    0x5EE00u, 0x59C00u, 0x67000u, 0x7C000u, 0xFFFFFu
};

// =====================================================================
// Kernel 1: per-channel CNN. 512 threads = 16 warps = 16 samples/block.
// Same arithmetic as the validated R6 version; conv2 weights staged in
// smem (pitch 33 -> conflict-free stores AND loads, coalesced LDG in).
// =====================================================================
#define K1_WARPS 16
__global__ __launch_bounds__(32 * K1_WARPS) void k1_cnn(
    const float* __restrict__ x, const float* __restrict__ pos_emb,
    const float* __restrict__ c1w, const float* __restrict__ c1b,
    const float* __restrict__ c2w, const float* __restrict__ c2b)
{
    __shared__ float s_w2T[160 * 33];            // [t=ic*5+k][oc], pitch 33
    __shared__ float s_c1w[160], s_c1b[32], s_c2b[32];
    __shared__ float s_p1[K1_WARPS][32][20];

    const int tid = threadIdx.x, ls = tid >> 5, oc = tid & 31;

    // coalesced read of c2w (oc-major), conflict-free padded store
    for (int i = tid; i < 5120; i += 32 * K1_WARPS) {
        int woc = i / 160, t = i - woc * 160;
        s_w2T[t * 33 + woc] = c2w[i];
    }
    if (tid < 160) s_c1w[tid] = c1w[tid];
    if (tid < 32) { s_c1b[tid] = c1b[tid]; s_c2b[tid] = c2b[tid]; }
    __syncthreads();

    const int s = blockIdx.x * K1_WARPS + ls;    // sample id < NSAMP (exact)
    const float* xp = x + (size_t)s * 200;

    const float w0 = s_c1w[oc * 5 + 0], w1v = s_c1w[oc * 5 + 1], w2v = s_c1w[oc * 5 + 2],
                w3v = s_c1w[oc * 5 + 3], w4v = s_c1w[oc * 5 + 4];
    const float b1v = s_c1b[oc];

#pragma unroll
    for (int j = 0; j < 20; j++) {
        const float* xx = xp + 10 * j;           // warp-broadcast loads
        float o0 = b1v, o1 = b1v;
        o0 = fmaf(xx[0], w0,  o0); o0 = fmaf(xx[1], w1v, o0);
        o0 = fmaf(xx[2], w2v, o0); o0 = fmaf(xx[3], w3v, o0);
        o0 = fmaf(xx[4], w4v, o0);
        o1 = fmaf(xx[5], w0,  o1); o1 = fmaf(xx[6], w1v, o1);
        o1 = fmaf(xx[7], w2v, o1); o1 = fmaf(xx[8], w3v, o1);
        o1 = fmaf(xx[9], w4v, o1);
        s_p1[ls][oc][j] = fmaxf(fmaxf(o0, o1), 0.f);
    }
    __syncwarp();

    float acc[8];
    const float b2v = s_c2b[oc];
#pragma unroll
    for (int p = 0; p < 8; p++) acc[p] = b2v;

    for (int ic = 0; ic < 32; ic++) {
        const int t0 = ic * 5;
        const float u0 = s_w2T[(t0 + 0) * 33 + oc];
        const float u1 = s_w2T[(t0 + 1) * 33 + oc];
        const float u2 = s_w2T[(t0 + 2) * 33 + oc];
        const float u3 = s_w2T[(t0 + 3) * 33 + oc];
        const float u4 = s_w2T[(t0 + 4) * 33 + oc];
        const float* pr = s_p1[ls][ic];          // broadcast reads
#pragma unroll
        for (int p = 0; p < 8; p++) {
            float a = acc[p];
            a = fmaf(pr[2 * p + 0], u0, a);
            a = fmaf(pr[2 * p + 1], u1, a);
            a = fmaf(pr[2 * p + 2], u2, a);
            a = fmaf(pr[2 * p + 3], u3, a);
            a = fmaf(pr[2 * p + 4], u4, a);
            acc[p] = a;
        }
    }
    float f = 0.f;
#pragma unroll
    for (int j = 0; j < 4; j++)
        f += fmaxf(fmaxf(acc[2 * j], 0.f), fmaxf(acc[2 * j + 1], 0.f));
    f *= 0.25f;

    const int bt = s / 19, c = s - bt * 19;
    g_tok[bt * 608 + c * 32 + oc] = f + pos_emb[c * 32 + oc];
}

// =====================================================================
// Kernel 2: transformer layer. ONE bt per block, 640 threads.
// Identical logic to the passing R6 version; all transposed weight
// regions padded to odd pitch -> conflict-free stores and loads.
// =====================================================================
#define SM_WQT  0              // 32x33 = 1056
#define SM_WKT  1056
#define SM_WVT  2112
#define SM_WOT  3168
#define SM_W1T  4224           // 32x129 = 4128
#define SM_W2T  8352           // 128x33 = 4224
#define SM_BQ   12576
#define SM_BK   12608
#define SM_BV   12640
#define SM_BO   12672
#define SM_B1   12704          // 128
#define SM_B2   12832
#define SM_LN1G 12864
#define SM_LN1B 12896
#define SM_LN2G 12928
#define SM_LN2B 12960
#define SM_TOK  12992          // 20x33 = 660
#define SM_Q    13652
#define SM_K    14312
#define SM_V    14972
#define SM_ATTN 15632
#define SM_TOK2 16292
#define SM_HIDN 16952          // 20x129 = 2580
#define SM_RES  19532          // 660
#define K2_SMEM_FLOATS 20192
#define K2_SMEM_BYTES  (K2_SMEM_FLOATS * 4)

__global__ __launch_bounds__(640) void k2_transformer(
    const float* __restrict__ pos_emb,
    const float* __restrict__ wq, const float* __restrict__ bq,
    const float* __restrict__ wk, const float* __restrict__ bk,
    const float* __restrict__ wv, const float* __restrict__ bv,
    const float* __restrict__ wo, const float* __restrict__ bo,
    const float* __restrict__ ln1g, const float* __restrict__ ln1b,
    const float* __restrict__ w1,  const float* __restrict__ b1,
    const float* __restrict__ w2,  const float* __restrict__ b2,
    const float* __restrict__ ln2g, const float* __restrict__ ln2b,
    float* __restrict__ out_hc)
{
    extern __shared__ float sm[];
    const int tid = threadIdx.x;
    const int bt  = blockIdx.x;

    // ---- transpose-on-load (coalesced LDG, padded conflict-free STS) ----
    for (int i = tid; i < 1024; i += 640) {
        int d = i >> 5, j = i & 31;              // src[d][j]
        sm[SM_WQT + j * 33 + d] = wq[i];
        sm[SM_WKT + j * 33 + d] = wk[i];
        sm[SM_WVT + j * 33 + d] = wv[i];
        sm[SM_WOT + j * 33 + d] = wo[i];
    }
    for (int i = tid; i < 4096; i += 640) {
        int h = i >> 5, j = i & 31;              // w1[h][j]
        sm[SM_W1T + j * 129 + h] = w1[i];
    }
    for (int i = tid; i < 4096; i += 640) {
        int d = i >> 7, h = i & 127;             // w2[d][h]
        sm[SM_W2T + h * 33 + d] = w2[i];
    }
    if (tid < 32) {
        sm[SM_BQ + tid] = bq[tid];   sm[SM_BK + tid] = bk[tid];
        sm[SM_BV + tid] = bv[tid];   sm[SM_BO + tid] = bo[tid];
        sm[SM_B2 + tid] = b2[tid];
        sm[SM_LN1G + tid] = ln1g[tid]; sm[SM_LN1B + tid] = ln1b[tid];
        sm[SM_LN2G + tid] = ln2g[tid]; sm[SM_LN2B + tid] = ln2b[tid];
    } else if (tid >= 64 && tid < 192) {
        sm[SM_B1 + tid - 64] = b1[tid - 64];
    }
    // tokens: r<19 from CNN, r=19 = pos_emb row 19
    {
        int r = tid >> 5, d = tid & 31;          // tid < 640 -> r < 20
        float v = (r < 19) ? g_tok[bt * 608 + r * 32 + d] : pos_emb[608 + d];
        sm[SM_TOK + r * 33 + d] = v;
    }
    __syncthreads();

    // ---- QKV ----
    {
        int r = tid >> 5, d = tid & 31;
        float aq = sm[SM_BQ + d], ak = sm[SM_BK + d], av = sm[SM_BV + d];
#pragma unroll
        for (int j = 0; j < 32; j++) {
            float b = sm[SM_TOK + r * 33 + j];
            aq = fmaf(b, sm[SM_WQT + j * 33 + d], aq);
            ak = fmaf(b, sm[SM_WKT + j * 33 + d], ak);
            av = fmaf(b, sm[SM_WVT + j * 33 + d], av);
        }
        sm[SM_Q + r * 33 + d] = aq;
        sm[SM_K + r * 33 + d] = ak;
        sm[SM_V + r * 33 + d] = av;
    }
    __syncthreads();

    // ---- masked attention: thread (qi, head), tid < 160 ----
    if (tid < 160) {
        int qi = tid >> 3, h4 = (tid & 7) << 2;
        float q0 = sm[SM_Q + qi * 33 + h4 + 0] * 0.5f;   // 1/sqrt(4) folded
        float q1 = sm[SM_Q + qi * 33 + h4 + 1] * 0.5f;
        float q2 = sm[SM_Q + qi * 33 + h4 + 2] * 0.5f;
        float q3 = sm[SM_Q + qi * 33 + h4 + 3] * 0.5f;
        unsigned msk = MASK20[qi];
        float l[20], mx = -3.0e38f;
#pragma unroll
        for (int kt = 0; kt < 20; kt++) {
            float sc = q0 * sm[SM_K + kt * 33 + h4 + 0];
            sc = fmaf(q1, sm[SM_K + kt * 33 + h4 + 1], sc);
            sc = fmaf(q2, sm[SM_K + kt * 33 + h4 + 2], sc);
            sc = fmaf(q3, sm[SM_K + kt * 33 + h4 + 3], sc);
            l[kt] = ((msk >> kt) & 1u) ? sc : -1.0e9f;
            mx = fmaxf(mx, l[kt]);
        }
        float sum = 0.f;
#pragma unroll
        for (int kt = 0; kt < 20; kt++) { l[kt] = __expf(l[kt] - mx); sum += l[kt]; }
        float inv = 1.f / sum;
#pragma unroll
        for (int d = 0; d < 4; d++) {
            float a = 0.f;
#pragma unroll
            for (int kt = 0; kt < 20; kt++)
                a = fmaf(l[kt], sm[SM_V + kt * 33 + h4 + d], a);
            sm[SM_ATTN + qi * 33 + h4 + d] = a * inv;
        }
    }
    __syncthreads();

    // ---- attn @ woT + bo + residual -> RES ----
    {
        int r = tid >> 5, d = tid & 31;
        float acc = sm[SM_BO + d];
#pragma unroll
        for (int j = 0; j < 32; j++)
            acc = fmaf(sm[SM_ATTN + r * 33 + j], sm[SM_WOT + j * 33 + d], acc);
        sm[SM_RES + r * 33 + d] = sm[SM_TOK + r * 33 + d] + acc;
    }
    __syncthreads();

    // ---- LayerNorm1 (one thread per token) ----
    if (tid < 20) {
        const int r = tid;
        float mu = 0.f;
#pragma unroll
        for (int d = 0; d < 32; d++) mu += sm[SM_RES + r * 33 + d];
        mu *= 0.03125f;
        float var = 0.f;
#pragma unroll
        for (int d = 0; d < 32; d++) {
            float t = sm[SM_RES + r * 33 + d] - mu; var = fmaf(t, t, var);
        }
        var *= 0.03125f;
        float rinv = rsqrtf(var + 1e-5f);
#pragma unroll
        for (int d = 0; d < 32; d++)
            sm[SM_TOK2 + r * 33 + d] =
                (sm[SM_RES + r * 33 + d] - mu) * rinv * sm[SM_LN1G + d] + sm[SM_LN1B + d];
    }
    __syncthreads();

    // ---- FF1 (32->128, relu): 2560 outputs, 4 per thread ----
#pragma unroll
    for (int p = 0; p < 4; p++) {
        int idx = tid + p * 640;          // < 2560
        int r = idx >> 7, h = idx & 127;
        float acc = sm[SM_B1 + h];
#pragma unroll
        for (int j = 0; j < 32; j++)
            acc = fmaf(sm[SM_TOK2 + r * 33 + j], sm[SM_W1T + j * 129 + h], acc);
        sm[SM_HIDN + r * 129 + h] = fmaxf(acc, 0.f);
    }
    __syncthreads();

    // ---- FF2 (128->32) + residual -> RES ----
    {
        int r = tid >> 5, d = tid & 31;
        float acc = sm[SM_B2 + d];
#pragma unroll
        for (int j = 0; j < 128; j++)
            acc = fmaf(sm[SM_HIDN + r * 129 + j], sm[SM_W2T + j * 33 + d], acc);
        sm[SM_RES + r * 33 + d] = sm[SM_TOK2 + r * 33 + d] + acc;
    }
    __syncthreads();

    // ---- LayerNorm2 -> global outputs (one thread per token) ----
    if (tid < 20) {
        const int r = tid;
        float mu = 0.f;
#pragma unroll
        for (int d = 0; d < 32; d++) mu += sm[SM_RES + r * 33 + d];
        mu *= 0.03125f;
        float var = 0.f;
#pragma unroll
        for (int d = 0; d < 32; d++) {
            float t = sm[SM_RES + r * 33 + d] - mu; var = fmaf(t, t, var);
        }
        var *= 0.03125f;
        float rinv = rsqrtf(var + 1e-5f);
#pragma unroll
        for (int d = 0; d < 32; d++) {
            float o = (sm[SM_RES + r * 33 + d] - mu) * rinv * sm[SM_LN2G + d] + sm[SM_LN2B + d];
            if (r < 19) out_hc[bt * 608 + r * 32 + d] = o;
            else        g_hm[bt * 32 + d] = o;
        }
    }
}

// =====================================================================
// Kernel 3: BiLSTM, 1 block per sequence, 128 threads. (unchanged)
// =====================================================================
__global__ __launch_bounds__(128) void k3_lstm(
    const float* __restrict__ wih_f, const float* __restrict__ whh_f,
    const float* __restrict__ bih_f, const float* __restrict__ bhh_f,
    const float* __restrict__ wih_b, const float* __restrict__ whh_b,
    const float* __restrict__ bih_b, const float* __restrict__ bhh_b)
{
    __shared__ float s_hm[TSEQ * 32];
    __shared__ float s_g[2][64];
    __shared__ float s_h[2][16];

    const int tid = threadIdx.x;
    const int dir = tid >> 6;            // 0 fwd, 1 bwd
    const int j   = tid & 63;            // gate row 0..63
    const int seq = blockIdx.x;

    for (int i = tid; i < TSEQ * 32; i += 128)
        s_hm[i] = g_hm[seq * TSEQ * 32 + i];

    const float* wih = dir ? wih_b : wih_f;
    const float* whh = dir ? whh_b : whh_f;
    const float* bih = dir ? bih_b : bih_f;
    const float* bhh = dir ? bhh_b : bhh_f;

    float wx[32], wh[16];
#pragma unroll
    for (int k = 0; k < 32; k++) wx[k] = wih[j * 32 + k];
#pragma unroll
    for (int k = 0; k < 16; k++) wh[k] = whh[j * 16 + k];
    const float bias = bih[j] + bhh[j];

    if (j < 16) s_h[dir][j] = 0.f;
    float c = 0.f;
    __syncthreads();

    for (int step = 0; step < TSEQ; step++) {
        const int t = dir ? (TSEQ - 1 - step) : step;
        float g = bias;
        const float* xp = &s_hm[t * 32];
#pragma unroll
        for (int k = 0; k < 32; k++) g = fmaf(xp[k], wx[k], g);
#pragma unroll
        for (int k = 0; k < 16; k++) g = fmaf(s_h[dir][k], wh[k], g);
        s_g[dir][j] = g;
        __syncthreads();
        if (j < 16) {
            float ig = 1.f / (1.f + __expf(-s_g[dir][j]));
            float ff = 1.f / (1.f + __expf(-s_g[dir][16 + j]));
            float gg = tanhf(s_g[dir][32 + j]);
            float oo = 1.f / (1.f + __expf(-s_g[dir][48 + j]));
            c = ff * c + ig * gg;
            float h = oo * tanhf(c);
            s_h[dir][j] = h;
            g_h[dir * (NSEQ * TSEQ * HID) + (seq * TSEQ + t) * HID + j] = h;
        }
        __syncthreads();
    }
}

// =====================================================================
// Kernel 4: final linear head. block = seq, thread = t. (unchanged)
// =====================================================================
__global__ __launch_bounds__(TSEQ) void k4_linear(
    const float* __restrict__ lin_w,
    const float* __restrict__ lin_b,
    float* __restrict__ out)
{
    const int seq = blockIdx.x, t = threadIdx.x;
    const int bt = seq * TSEQ + t;
    const float* hf = &g_h[bt * HID];
    const float* hb = &g_h[NSEQ * TSEQ * HID + bt * HID];
    float a0 = lin_b[0], a1 = lin_b[1];
#pragma unroll
    for (int j = 0; j < 16; j++) {
        float f = hf[j], b = hb[j];
        a0 = fmaf(f, lin_w[j],      a0);
        a0 = fmaf(b, lin_w[16 + j], a0);
        a1 = fmaf(f, lin_w[32 + j], a1);
        a1 = fmaf(b, lin_w[48 + j], a1);
    }
    out[bt * 2 + 0] = a0;
    out[bt * 2 + 1] = a1;
}

// =====================================================================
extern "C" void kernel_launch(void* const* d_in, const int* in_sizes, int n_in,
                              void* d_out, int out_size)
{
    const float* x       = (const float*)d_in[0];
    const float* pos_emb = (const float*)d_in[1];
    const float* c1w     = (const float*)d_in[2];
    const float* c1b     = (const float*)d_in[3];
    const float* c2w     = (const float*)d_in[4];
    const float* c2b     = (const float*)d_in[5];
    const float* wq      = (const float*)d_in[6];
    const float* bq      = (const float*)d_in[7];
    const float* wk      = (const float*)d_in[8];
    const float* bk      = (const float*)d_in[9];
    const float* wv      = (const float*)d_in[10];
    const float* bv      = (const float*)d_in[11];
    const float* wo      = (const float*)d_in[12];
    const float* bo      = (const float*)d_in[13];
    const float* ln1g    = (const float*)d_in[14];
    const float* ln1b    = (const float*)d_in[15];
    const float* w1      = (const float*)d_in[16];
    const float* b1      = (const float*)d_in[17];
    const float* w2      = (const float*)d_in[18];
    const float* b2      = (const float*)d_in[19];
    const float* ln2g    = (const float*)d_in[20];
    const float* ln2b    = (const float*)d_in[21];
    const float* wih_f   = (const float*)d_in[22];
    const float* whh_f   = (const float*)d_in[23];
    const float* bih_f   = (const float*)d_in[24];
    const float* bhh_f   = (const float*)d_in[25];
    const float* wih_b   = (const float*)d_in[26];
    const float* whh_b   = (const float*)d_in[27];
    const float* bih_b   = (const float*)d_in[28];
    const float* bhh_b   = (const float*)d_in[29];
    const float* lin_w   = (const float*)d_in[30];
    const float* lin_b   = (const float*)d_in[31];

    float* out = (float*)d_out;   // [0,7680): proba ; [7680,...): h_c_out

    cudaFuncSetAttribute(k2_transformer,
                         cudaFuncAttributeMaxDynamicSharedMemorySize,
                         K2_SMEM_BYTES);

    k1_cnn<<<NSAMP / K1_WARPS, 32 * K1_WARPS>>>(x, pos_emb, c1w, c1b, c2w, c2b);
    k2_transformer<<<BT_TOT, 640, K2_SMEM_BYTES>>>(
        pos_emb, wq, bq, wk, bk, wv, bv, wo, bo,
        ln1g, ln1b, w1, b1, w2, b2, ln2g, ln2b,
        out + 7680);
    k3_lstm<<<NSEQ, 128>>>(wih_f, whh_f, bih_f, bhh_f,
                           wih_b, whh_b, bih_b, bhh_b);
    k4_linear<<<NSEQ, TSEQ>>>(lin_w, lin_b, out);
}